// round 13
// baseline (speedup 1.0000x reference)
#include <cuda_runtime.h>
#include <cuda_bf16.h>
#include <math.h>
#include <stdint.h>

#define NROWS 500000
#define KDIM 256
#define BM 128
#define NCHUNK 8

typedef unsigned long long ull;
typedef uint32_t u32;

// ---- smem: full A image (8 chunks x 16KB) + epilogue staging ----
#define OFF_A(c)  ((c) * 16384)          // [chunk][row][128B: hi 64 | lo 64], swizzled
#define OFF_W2P   131072                  // 128 col-pairs x 80B = 10240
#define OFF_B1P   141312                  // 128 ull pairs = 1024
#define OFF_PBUF  142336                  // 128 x 4 x 9 floats = 18432
#define SMEM_TOTAL 160768

// W1 in mma-fragment order (verified R11/R12): [chunk][ks][h][jj] blocks of 512B
__device__ unsigned char g_Bfrag[8 * 2 * 2 * 16 * 512];   // 256 KB

__device__ __forceinline__ u32 smem_u32(const void* p) {
    u32 a;
    asm("{ .reg .u64 t; cvta.to.shared.u64 t, %1; cvt.u32.u64 %0, t; }" : "=r"(a) : "l"(p));
    return a;
}

// ---- packed f32x2 ----
__device__ __forceinline__ ull pk2(float x, float y) {
    ull r;
    asm("mov.b64 %0, {%1, %2};" : "=l"(r) : "r"(__float_as_uint(x)), "r"(__float_as_uint(y)));
    return r;
}
__device__ __forceinline__ void upk2(ull v, float &x, float &y) {
    unsigned lo, hi;
    asm("mov.b64 {%0, %1}, %2;" : "=r"(lo), "=r"(hi) : "l"(v));
    x = __uint_as_float(lo); y = __uint_as_float(hi);
}
__device__ __forceinline__ ull ffma2(ull a, ull b, ull c) {
    ull d;
    asm("fma.rn.f32x2 %0, %1, %2, %3;" : "=l"(d) : "l"(a), "l"(b), "l"(c));
    return d;
}

__device__ __forceinline__ u32 pack_bf16x2(float even, float odd) {
    u32 r;
    asm("cvt.rn.bf16x2.f32 %0, %1, %2;" : "=r"(r) : "f"(odd), "f"(even));
    return r;
}
__device__ __forceinline__ void split_bf(float x, u32 &hibits, float &lo) {
    u32 b = __float_as_uint(x) & 0xFFFF0000u;
    hibits = b;
    lo = x - __uint_as_float(b);
}

// ---- B fragment load ----
__device__ __forceinline__ void ldg4nc(u32 r[4], const void* g) {
    asm volatile("ld.global.nc.v4.u32 {%0,%1,%2,%3}, [%4];"
                 : "=r"(r[0]), "=r"(r[1]), "=r"(r[2]), "=r"(r[3]) : "l"(g));
}

// ---- ldmatrix / mma.sync ----
__device__ __forceinline__ void ldsm4(u32 r[4], u32 addr) {
    asm volatile("ldmatrix.sync.aligned.m8n8.x4.shared.b16 {%0,%1,%2,%3}, [%4];"
                 : "=r"(r[0]), "=r"(r[1]), "=r"(r[2]), "=r"(r[3]) : "r"(addr));
}
__device__ __forceinline__ void mma16816(float c[4], const u32 a[4], u32 b0, u32 b1) {
    asm volatile("mma.sync.aligned.m16n8k16.row.col.f32.bf16.bf16.f32 "
                 "{%0,%1,%2,%3}, {%4,%5,%6,%7}, {%8,%9}, {%0,%1,%2,%3};"
                 : "+f"(c[0]), "+f"(c[1]), "+f"(c[2]), "+f"(c[3])
                 : "r"(a[0]), "r"(a[1]), "r"(a[2]), "r"(a[3]), "r"(b0), "r"(b1));
}

// ---- geometry (verified) ----
__device__ __forceinline__ void accp_normalize(const float raw[3], const float rawa[3][3],
                                               float t[3], float ta[3][3]) {
    float ss = raw[0]*raw[0] + raw[1]*raw[1] + raw[2]*raw[2];
    float nrm = sqrtf(ss);
    float inv = 1.0f / nrm;
    float inv2 = inv * inv;
#pragma unroll
    for (int k = 0; k < 3; k++) {
        float ssa = 2.0f * (rawa[k][0]*raw[0] + rawa[k][1]*raw[1] + rawa[k][2]*raw[2]);
        float nrma = ssa * (0.5f * inv);
        float inva = -nrma * inv2;
#pragma unroll
        for (int a = 0; a < 3; a++) ta[k][a] = inva * raw[a] + inv * rawa[k][a];
    }
#pragma unroll
    for (int a = 0; a < 3; a++) t[a] = inv * raw[a];
}

// ============ prep: W1 -> mma fragment image (verified, unchanged) ============
__global__ void prep_bfrag(const float* __restrict__ W1) {
    int idx = blockIdx.x * blockDim.x + threadIdx.x;   // 16384
    int lane = idx & 31;
    int jj   = (idx >> 5) & 15;
    int h    = (idx >> 9) & 1;
    int ks   = (idx >> 10) & 1;
    int c    = idx >> 11;
    int tig = lane & 3, gid = lane >> 2;
    int kb = c * 32 + ks * 16 + 2 * tig;
    int n0 = 2 * jj * 8 + gid;
    int n1 = n0 + 8;

    u32 r[4];
#pragma unroll
    for (int q = 0; q < 4; q++) {
        int k = kb + ((q & 1) ? 8 : 0);
        int n = (q >> 1) ? n1 : n0;
        float x0 = W1[(size_t)k * 256 + n];
        float x1 = W1[(size_t)(k + 1) * 256 + n];
        u32 h0, h1; float l0, l1;
        split_bf(x0, h0, l0);
        split_bf(x1, h1, l1);
        r[q] = h ? pack_bf16x2(l0, l1) : ((h1 & 0xFFFF0000u) | (h0 >> 16));
    }
    u32* dst = (u32*)(g_Bfrag + ((size_t)(((c * 2 + ks) * 2 + h) * 16 + jj)) * 512 + lane * 16);
    dst[0] = r[0]; dst[1] = r[1]; dst[2] = r[2]; dst[3] = r[3];
}

// ============ main: full-A smem staging, then barrier-free mainloop ============
__global__ __launch_bounds__(512, 1)
void cond9_mma_kernel(const float* __restrict__ rot,
                      const float* __restrict__ feat,
                      const float* __restrict__ b1g,
                      const float* __restrict__ W2g,
                      const float* __restrict__ b2g,
                      float* __restrict__ out) {
    extern __shared__ unsigned char smem[];
    const u32 sb = smem_u32(smem);
    const int tid = threadIdx.x;
    const int lane = tid & 31;
    const int wid = tid >> 5;
    const int wm = wid & 3;        // M warp (4 x 32 rows)
    const int wn = wid >> 2;       // N warp (4 x 64 cols)
    const int g = lane >> 2;       // mma group id
    const int tg = lane & 3;       // mma thread-in-group
    const int lmrow = lane & 15;
    const int lmhalf = lane >> 4;
    const int rowBase = blockIdx.x * BM;

    // ---- stage W2 pairs + b1 pairs ----
    for (int idx = tid; idx < 128 * 9; idx += 512) {
        int jp = idx / 9, t = idx - jp * 9;
        float w0 = W2g[(size_t)(2*jp)   * 9 + t];
        float w1 = W2g[(size_t)(2*jp+1) * 9 + t];
        *(ull*)(smem + OFF_W2P + jp * 80 + t * 8) = pk2(w0, w1);
    }
    if (tid < 128)
        *(ull*)(smem + OFF_B1P + tid * 8) = pk2(b1g[2*tid], b1g[2*tid + 1]);

    // ---- stage ALL of A (128 rows x 256 k), split hi/lo, swizzled (R9 image) ----
    for (int idx = tid; idx < 8192; idx += 512) {
        int row = idx >> 6;          // 0..127
        int kq  = idx & 63;          // float4 index within row
        int r = rowBase + row;
        if (r > NROWS - 1) r = NROWS - 1;
        float4 v = __ldg((const float4*)(feat + (size_t)r * KDIM + kq * 4));
        int c = kq >> 3, q = kq & 7;
        u32 h0, h1, h2, h3; float l0, l1, l2, l3;
        split_bf(v.x, h0, l0); split_bf(v.y, h1, l1);
        split_bf(v.z, h2, l2); split_bf(v.w, h3, l3);
        u32 hp0 = (h1 & 0xFFFF0000u) | (h0 >> 16);
        u32 hp1 = (h3 & 0xFFFF0000u) | (h2 >> 16);
        u32 lp0 = pack_bf16x2(l0, l1);
        u32 lp1 = pack_bf16x2(l2, l3);
        u32 rb = sb + OFF_A(c) + (u32)row * 128;
        u32 ah = rb + ((((q >> 1)    ) ^ (row & 7)) << 4) + (q & 1) * 8;
        u32 al = rb + ((((q >> 1) + 4) ^ (row & 7)) << 4) + (q & 1) * 8;
        asm volatile("st.shared.v2.b32 [%0], {%1,%2};" :: "r"(ah), "r"(hp0), "r"(hp1));
        asm volatile("st.shared.v2.b32 [%0], {%1,%2};" :: "r"(al), "r"(lp0), "r"(lp1));
    }
    __syncthreads();   // the ONLY pre-epilogue barrier

    float acc[2][8][4];
#pragma unroll
    for (int mt = 0; mt < 2; mt++)
#pragma unroll
        for (int nt = 0; nt < 8; nt++)
#pragma unroll
            for (int q = 0; q < 4; q++) acc[mt][nt][q] = 0.0f;

    const unsigned char* bfr = g_Bfrag + ((size_t)(wn * 4)) * 512 + (size_t)lane * 16;

    // ---- barrier-free mainloop: ldsm A + fragment-LDG B + HMMA ----
    for (int c = 0; c < NCHUNK; ++c) {
        const u32 aB = sb + OFF_A(c);
#pragma unroll
        for (int ks = 0; ks < 2; ks++) {
            const unsigned char* bk = bfr + (size_t)((c * 2 + ks) * 2) * 16 * 512;

            u32 BH[4][4];
#pragma unroll
            for (int j = 0; j < 4; j++) ldg4nc(BH[j], bk + (size_t)j * 512);

            u32 AH[2][4], AL[2][4];
#pragma unroll
            for (int mt = 0; mt < 2; mt++) {
                int row = wm * 32 + mt * 16 + lmrow;
                u32 rb = aB + (u32)row * 128;
                ldsm4(AH[mt], rb + (((ks * 2 + lmhalf    ) ^ (row & 7)) << 4));
                ldsm4(AL[mt], rb + (((ks * 2 + lmhalf + 4) ^ (row & 7)) << 4));
            }

            // HH
#pragma unroll
            for (int mt = 0; mt < 2; mt++)
#pragma unroll
                for (int j = 0; j < 4; j++) {
                    mma16816(acc[mt][2*j],   AH[mt], BH[j][0], BH[j][1]);
                    mma16816(acc[mt][2*j+1], AH[mt], BH[j][2], BH[j][3]);
                }
            // B-lo loads; latency hidden under LH mmas
            u32 BL[4][4];
#pragma unroll
            for (int j = 0; j < 4; j++) ldg4nc(BL[j], bk + (size_t)(16 + j) * 512);
            // LH
#pragma unroll
            for (int mt = 0; mt < 2; mt++)
#pragma unroll
                for (int j = 0; j < 4; j++) {
                    mma16816(acc[mt][2*j],   AL[mt], BH[j][0], BH[j][1]);
                    mma16816(acc[mt][2*j+1], AL[mt], BH[j][2], BH[j][3]);
                }
            // HL
#pragma unroll
            for (int mt = 0; mt < 2; mt++)
#pragma unroll
                for (int j = 0; j < 4; j++) {
                    mma16816(acc[mt][2*j],   AH[mt], BL[j][0], BL[j][1]);
                    mma16816(acc[mt][2*j+1], AH[mt], BL[j][2], BL[j][3]);
                }
        }
    }

    // ---- epilogue: bias+relu, h@W2 partials, cross-warp reduce ----
    const ull* b1p = (const ull*)(smem + OFF_B1P);
    float* pbuf = (float*)(smem + OFF_PBUF);

#pragma unroll
    for (int mt = 0; mt < 2; mt++) {
#pragma unroll
        for (int s = 0; s < 2; s++) {
            ull p[9];
#pragma unroll
            for (int t = 0; t < 9; t++) p[t] = 0ull;
#pragma unroll
            for (int nt = 0; nt < 8; nt++) {
                int jp = wn * 32 + nt * 4 + tg;
                float bb0, bb1;
                upk2(b1p[jp], bb0, bb1);
                float h0 = fmaxf(acc[mt][nt][2*s]     + bb0, 0.0f);
                float h1 = fmaxf(acc[mt][nt][2*s + 1] + bb1, 0.0f);
                ull hp = pk2(h0, h1);
                const ull* wr = (const ull*)(smem + OFF_W2P + (size_t)jp * 80);
#pragma unroll
                for (int t = 0; t < 9; t++) p[t] = ffma2(hp, wr[t], p[t]);
            }
            float q[9];
#pragma unroll
            for (int t = 0; t < 9; t++) {
                float a, b;
                upk2(p[t], a, b);
                float v = a + b;
                v += __shfl_xor_sync(0xffffffffu, v, 1);
                v += __shfl_xor_sync(0xffffffffu, v, 2);
                q[t] = v;
            }
            if (tg == 0) {
                int row = wm * 32 + mt * 16 + 8 * s + g;
#pragma unroll
                for (int t = 0; t < 9; t++)
                    pbuf[(row * 4 + wn) * 9 + t] = q[t];
            }
        }
    }
    __syncthreads();

    if (tid < 128) {
        int myrow = rowBase + tid;
        if (myrow < NROWS) {
            float m9[9];
#pragma unroll
            for (int t = 0; t < 9; t++)
                m9[t] = pbuf[(tid * 4 + 0) * 9 + t] + pbuf[(tid * 4 + 1) * 9 + t]
                      + pbuf[(tid * 4 + 2) * 9 + t] + pbuf[(tid * 4 + 3) * 9 + t];

            float mat[3][3];
#pragma unroll
            for (int a = 0; a < 3; a++)
#pragma unroll
                for (int b = 0; b < 3; b++)
                    mat[a][b] = m9[a*3 + b] + __ldg(&b2g[a*3 + b]) + (a == b ? 1.0f : 0.0f);

            float rt[3][3];
#pragma unroll
            for (int a = 0; a < 3; a++)
#pragma unroll
                for (int b = 0; b < 3; b++)
                    rt[a][b] = __ldg(&rot[(size_t)myrow * 9 + a*3 + b]);

            float rm[3][3];
#pragma unroll
            for (int a = 0; a < 3; a++)
#pragma unroll
                for (int cc = 0; cc < 3; cc++)
                    rm[a][cc] = mat[a][0]*rt[0][cc] + mat[a][1]*rt[1][cc] + mat[a][2]*rt[2][cc];

            float c0[3], c1[3], c0a[3][3], c1a[3][3];
#pragma unroll
            for (int a = 0; a < 3; a++) {
                c0[a] = rm[a][0];
                c1[a] = rm[a][1];
                c0a[0][a] = -rm[a][1];
                c0a[1][a] = -rm[a][2];
                c0a[2][a] = 0.0f;
                c1a[0][a] = rm[a][0];
                c1a[1][a] = 0.0f;
                c1a[2][a] = -rm[a][2];
            }

            float t0[3], t0a[3][3];
            accp_normalize(c0, c0a, t0, t0a);

            float dot = t0[0]*c1[0] + t0[1]*c1[1] + t0[2]*c1[2];
            float raw1[3], raw1a[3][3];
#pragma unroll
            for (int a = 0; a < 3; a++) raw1[a] = c1[a] - dot * t0[a];
#pragma unroll
            for (int k = 0; k < 3; k++) {
                float dota = 0.0f;
#pragma unroll
                for (int a = 0; a < 3; a++)
                    dota += t0a[k][a]*c1[a] + t0[a]*c1a[k][a];
#pragma unroll
                for (int a = 0; a < 3; a++)
                    raw1a[k][a] = c1a[k][a] - (dota * t0[a] + dot * t0a[k][a]);
            }

            float t1[3], t1a[3][3];
            accp_normalize(raw1, raw1a, t1, t1a);

            const int P1[3] = {1, 2, 0};
            const int P2[3] = {2, 0, 1};
            float t2[3], t2a[3][3];
#pragma unroll
            for (int i = 0; i < 3; i++)
                t2[i] = t0[P1[i]]*t1[P2[i]] - t0[P2[i]]*t1[P1[i]];
#pragma unroll
            for (int k = 0; k < 3; k++)
#pragma unroll
                for (int i = 0; i < 3; i++)
                    t2a[k][i] = t0[P1[i]]*t1a[k][P2[i]] + t0a[k][P1[i]]*t1[P2[i]]
                              - t0[P2[i]]*t1a[k][P1[i]] - t0a[k][P2[i]]*t1[P1[i]];

            float vec[3][3];
#pragma unroll
            for (int k = 0; k < 3; k++) {
                vec[k][0] = t0a[k][0]*t0[1] + t1a[k][0]*t1[1] + t2a[k][0]*t2[1];
                vec[k][1] = t0a[k][0]*t0[2] + t1a[k][0]*t1[2] + t2a[k][0]*t2[2];
                vec[k][2] = t0a[k][1]*t0[2] + t1a[k][1]*t1[2] + t2a[k][1]*t2[2];
            }

            float d00 = vec[1][1]*vec[2][2] - vec[1][2]*vec[2][1];
            float d01 = vec[1][2]*vec[2][0] - vec[1][0]*vec[2][2];
            float d02 = vec[1][0]*vec[2][1] - vec[1][1]*vec[2][0];
            float det = d00*vec[0][0] + d01*vec[0][1] + d02*vec[0][2];
            float logdet = logf(fabsf(det));

            size_t ob = (size_t)myrow * 9;
            out[ob + 0] = t0[0]; out[ob + 1] = t1[0]; out[ob + 2] = t2[0];
            out[ob + 3] = t0[1]; out[ob + 4] = t1[1]; out[ob + 5] = t2[1];
            out[ob + 6] = t0[2]; out[ob + 7] = t1[2]; out[ob + 8] = t2[2];
            out[(size_t)9 * NROWS + myrow] = logdet;
        }
    }
}

extern "C" void kernel_launch(void* const* d_in, const int* in_sizes, int n_in,
                              void* d_out, int out_size) {
    const float* rot  = (const float*)d_in[0];  // rotation [N,3,3]
    const float* feat = (const float*)d_in[1];  // feature  [N,256]
    const float* W1   = (const float*)d_in[2];  // [256,256]
    const float* b1   = (const float*)d_in[3];  // [256]
    const float* W2   = (const float*)d_in[4];  // [256,9]
    const float* b2   = (const float*)d_in[5];  // [9]
    float* out = (float*)d_out;

    cudaFuncSetAttribute(cond9_mma_kernel,
                         cudaFuncAttributeMaxDynamicSharedMemorySize, SMEM_TOTAL);

    prep_bfrag<<<64, 256>>>(W1);
    int blocks = (NROWS + BM - 1) / BM;   // 3907
    cond9_mma_kernel<<<blocks, 512, SMEM_TOTAL>>>(rot, feat, b1, W2, b2, out);
}

// round 14
// speedup vs baseline: 1.1274x; 1.1274x over previous
#include <cuda_runtime.h>
#include <cuda_bf16.h>
#include <math.h>
#include <stdint.h>

#define NROWS 500000
#define KDIM 256
#define BM 64
#define NCHUNK 8

typedef unsigned long long ull;
typedef uint32_t u32;

// ---- smem: only epilogue staging (small => L1D stays ~187KB for B-frags) ----
#define OFF_W2P   0          // 128 col-pairs x 80B = 10240
#define OFF_B1P   10240      // 128 ull pairs = 1024
#define OFF_PBUF  11264      // 64 x 4 x 9 floats = 9216
#define SMEM_TOTAL 20480

// W1 in mma-fragment order (verified R11/R12): [chunk][ks][h][jj] blocks of 512B
__device__ unsigned char g_Bfrag[8 * 2 * 2 * 16 * 512];   // 256 KB

// ---- packed f32x2 ----
__device__ __forceinline__ ull pk2(float x, float y) {
    ull r;
    asm("mov.b64 %0, {%1, %2};" : "=l"(r) : "r"(__float_as_uint(x)), "r"(__float_as_uint(y)));
    return r;
}
__device__ __forceinline__ void upk2(ull v, float &x, float &y) {
    unsigned lo, hi;
    asm("mov.b64 {%0, %1}, %2;" : "=r"(lo), "=r"(hi) : "l"(v));
    x = __uint_as_float(lo); y = __uint_as_float(hi);
}
__device__ __forceinline__ ull ffma2(ull a, ull b, ull c) {
    ull d;
    asm("fma.rn.f32x2 %0, %1, %2, %3;" : "=l"(d) : "l"(a), "l"(b), "l"(c));
    return d;
}

__device__ __forceinline__ u32 pack_bf16x2(float even, float odd) {
    u32 r;
    asm("cvt.rn.bf16x2.f32 %0, %1, %2;" : "=r"(r) : "f"(odd), "f"(even));
    return r;
}
__device__ __forceinline__ void split_bf(float x, u32 &hibits, float &lo) {
    u32 b = __float_as_uint(x) & 0xFFFF0000u;
    hibits = b;
    lo = x - __uint_as_float(b);
}
// split a float2 (k, k+1) into packed bf16x2 hi + lo (bit-identical to R12)
__device__ __forceinline__ void split_pair(float2 p, u32 &hp, u32 &lp) {
    u32 h0, h1; float l0, l1;
    split_bf(p.x, h0, l0);
    split_bf(p.y, h1, l1);
    hp = (h1 & 0xFFFF0000u) | (h0 >> 16);
    lp = pack_bf16x2(l0, l1);
}

// ---- global fragment loads ----
__device__ __forceinline__ void ldg4nc(u32 r[4], const void* g) {
    asm volatile("ld.global.nc.v4.u32 {%0,%1,%2,%3}, [%4];"
                 : "=r"(r[0]), "=r"(r[1]), "=r"(r[2]), "=r"(r[3]) : "l"(g));
}
__device__ __forceinline__ float2 ldg2nc(const float* g) {
    float2 v;
    asm volatile("ld.global.nc.v2.f32 {%0,%1}, [%2];" : "=f"(v.x), "=f"(v.y) : "l"(g));
    return v;
}

__device__ __forceinline__ void mma16816(float c[4], const u32 a[4], u32 b0, u32 b1) {
    asm volatile("mma.sync.aligned.m16n8k16.row.col.f32.bf16.bf16.f32 "
                 "{%0,%1,%2,%3}, {%4,%5,%6,%7}, {%8,%9}, {%0,%1,%2,%3};"
                 : "+f"(c[0]), "+f"(c[1]), "+f"(c[2]), "+f"(c[3])
                 : "r"(a[0]), "r"(a[1]), "r"(a[2]), "r"(a[3]), "r"(b0), "r"(b1));
}

// ---- geometry (verified) ----
__device__ __forceinline__ void accp_normalize(const float raw[3], const float rawa[3][3],
                                               float t[3], float ta[3][3]) {
    float ss = raw[0]*raw[0] + raw[1]*raw[1] + raw[2]*raw[2];
    float nrm = sqrtf(ss);
    float inv = 1.0f / nrm;
    float inv2 = inv * inv;
#pragma unroll
    for (int k = 0; k < 3; k++) {
        float ssa = 2.0f * (rawa[k][0]*raw[0] + rawa[k][1]*raw[1] + rawa[k][2]*raw[2]);
        float nrma = ssa * (0.5f * inv);
        float inva = -nrma * inv2;
#pragma unroll
        for (int a = 0; a < 3; a++) ta[k][a] = inva * raw[a] + inv * rawa[k][a];
    }
#pragma unroll
    for (int a = 0; a < 3; a++) t[a] = inv * raw[a];
}

// ============ prep: W1 -> mma fragment image (verified, unchanged) ============
__global__ void prep_bfrag(const float* __restrict__ W1) {
    int idx = blockIdx.x * blockDim.x + threadIdx.x;   // 16384
    int lane = idx & 31;
    int jj   = (idx >> 5) & 15;
    int h    = (idx >> 9) & 1;
    int ks   = (idx >> 10) & 1;
    int c    = idx >> 11;
    int tig = lane & 3, gid = lane >> 2;
    int kb = c * 32 + ks * 16 + 2 * tig;
    int n0 = 2 * jj * 8 + gid;
    int n1 = n0 + 8;

    u32 r[4];
#pragma unroll
    for (int q = 0; q < 4; q++) {
        int k = kb + ((q & 1) ? 8 : 0);
        int n = (q >> 1) ? n1 : n0;
        float x0 = W1[(size_t)k * 256 + n];
        float x1 = W1[(size_t)(k + 1) * 256 + n];
        u32 h0, h1; float l0, l1;
        split_bf(x0, h0, l0);
        split_bf(x1, h1, l1);
        r[q] = h ? pack_bf16x2(l0, l1) : ((h1 & 0xFFFF0000u) | (h0 >> 16));
    }
    u32* dst = (u32*)(g_Bfrag + ((size_t)(((c * 2 + ks) * 2 + h) * 16 + jj)) * 512 + lane * 16);
    dst[0] = r[0]; dst[1] = r[1]; dst[2] = r[2]; dst[3] = r[3];
}

// ============ main: BM=64, 256 threads, 8 warps (2M x 4N), 2 CTAs/SM ============
__global__ __launch_bounds__(256, 2)
void cond9_mma_kernel(const float* __restrict__ rot,
                      const float* __restrict__ feat,
                      const float* __restrict__ b1g,
                      const float* __restrict__ W2g,
                      const float* __restrict__ b2g,
                      float* __restrict__ out) {
    extern __shared__ unsigned char smem[];
    const int tid = threadIdx.x;
    const int lane = tid & 31;
    const int wid = tid >> 5;
    const int wm = wid & 1;        // M warp (2 x 32 rows)
    const int wn = wid >> 1;       // N warp (4 x 64 cols)
    const int g = lane >> 2;       // mma group id
    const int tg = lane & 3;       // mma thread-in-group
    const int rowBase = blockIdx.x * BM;

    // ---- stage W2 pairs + b1 pairs ----
    for (int idx = tid; idx < 128 * 9; idx += 256) {
        int jp = idx / 9, t = idx - jp * 9;
        float w0 = W2g[(size_t)(2*jp)   * 9 + t];
        float w1 = W2g[(size_t)(2*jp+1) * 9 + t];
        *(ull*)(smem + OFF_W2P + jp * 80 + t * 8) = pk2(w0, w1);
    }
    if (tid < 128)
        *(ull*)(smem + OFF_B1P + tid * 8) = pk2(b1g[2*tid], b1g[2*tid + 1]);
    __syncthreads();

    float acc[2][8][4];
#pragma unroll
    for (int mt = 0; mt < 2; mt++)
#pragma unroll
        for (int nt = 0; nt < 8; nt++)
#pragma unroll
            for (int q = 0; q < 4; q++) acc[mt][nt][q] = 0.0f;

    // A fragment row pointers: per mt, rows (g, g+8) of this warp's 16-row tile
    const float* ar[2][2];
#pragma unroll
    for (int mt = 0; mt < 2; mt++) {
        int rb = rowBase + wm * 32 + mt * 16 + g;
        int ra = rb     < NROWS ? rb     : NROWS - 1;
        int rc = rb + 8 < NROWS ? rb + 8 : NROWS - 1;
        ar[mt][0] = feat + (size_t)ra * KDIM;
        ar[mt][1] = feat + (size_t)rc * KDIM;
    }

    const unsigned char* bfr = g_Bfrag + ((size_t)(wn * 4)) * 512 + (size_t)lane * 16;

    // ---- barrier-free mainloop (R12 structure, verbatim) ----
    for (int c = 0; c < NCHUNK; ++c) {
#pragma unroll
        for (int ks = 0; ks < 2; ks++) {
            const int k0 = c * 32 + ks * 16 + 2 * tg;
            const unsigned char* bk = bfr + (size_t)((c * 2 + ks) * 2) * 16 * 512;

            // B-hi fragment loads first (L1-resident at this smem footprint)
            u32 BH[4][4];
#pragma unroll
            for (int j = 0; j < 4; j++) ldg4nc(BH[j], bk + (size_t)j * 512);

            // A fragment loads + in-register split
            u32 AH[2][4], AL[2][4];
#pragma unroll
            for (int mt = 0; mt < 2; mt++) {
                float2 p0 = ldg2nc(ar[mt][0] + k0);
                float2 p1 = ldg2nc(ar[mt][1] + k0);
                float2 p2 = ldg2nc(ar[mt][0] + k0 + 8);
                float2 p3 = ldg2nc(ar[mt][1] + k0 + 8);
                split_pair(p0, AH[mt][0], AL[mt][0]);
                split_pair(p1, AH[mt][1], AL[mt][1]);
                split_pair(p2, AH[mt][2], AL[mt][2]);
                split_pair(p3, AH[mt][3], AL[mt][3]);
            }

            // HH
#pragma unroll
            for (int mt = 0; mt < 2; mt++)
#pragma unroll
                for (int j = 0; j < 4; j++) {
                    mma16816(acc[mt][2*j],   AH[mt], BH[j][0], BH[j][1]);
                    mma16816(acc[mt][2*j+1], AH[mt], BH[j][2], BH[j][3]);
                }
            // B-lo loads; latency hidden under LH mmas
            u32 BL[4][4];
#pragma unroll
            for (int j = 0; j < 4; j++) ldg4nc(BL[j], bk + (size_t)(16 + j) * 512);
            // LH
#pragma unroll
            for (int mt = 0; mt < 2; mt++)
#pragma unroll
                for (int j = 0; j < 4; j++) {
                    mma16816(acc[mt][2*j],   AL[mt], BH[j][0], BH[j][1]);
                    mma16816(acc[mt][2*j+1], AL[mt], BH[j][2], BH[j][3]);
                }
            // HL
#pragma unroll
            for (int mt = 0; mt < 2; mt++)
#pragma unroll
                for (int j = 0; j < 4; j++) {
                    mma16816(acc[mt][2*j],   AH[mt], BL[j][0], BL[j][1]);
                    mma16816(acc[mt][2*j+1], AH[mt], BL[j][2], BL[j][3]);
                }
        }
    }

    // ---- epilogue: bias+relu, h@W2 partials, cross-warp reduce ----
    const ull* b1p = (const ull*)(smem + OFF_B1P);
    float* pbuf = (float*)(smem + OFF_PBUF);

#pragma unroll
    for (int mt = 0; mt < 2; mt++) {
#pragma unroll
        for (int s = 0; s < 2; s++) {
            ull p[9];
#pragma unroll
            for (int t = 0; t < 9; t++) p[t] = 0ull;
#pragma unroll
            for (int nt = 0; nt < 8; nt++) {
                int jp = wn * 32 + nt * 4 + tg;
                float bb0, bb1;
                upk2(b1p[jp], bb0, bb1);
                float h0 = fmaxf(acc[mt][nt][2*s]     + bb0, 0.0f);
                float h1 = fmaxf(acc[mt][nt][2*s + 1] + bb1, 0.0f);
                ull hp = pk2(h0, h1);
                const ull* wr = (const ull*)(smem + OFF_W2P + (size_t)jp * 80);
#pragma unroll
                for (int t = 0; t < 9; t++) p[t] = ffma2(hp, wr[t], p[t]);
            }
            float q[9];
#pragma unroll
            for (int t = 0; t < 9; t++) {
                float a, b;
                upk2(p[t], a, b);
                float v = a + b;
                v += __shfl_xor_sync(0xffffffffu, v, 1);
                v += __shfl_xor_sync(0xffffffffu, v, 2);
                q[t] = v;
            }
            if (tg == 0) {
                int row = wm * 32 + mt * 16 + 8 * s + g;
#pragma unroll
                for (int t = 0; t < 9; t++)
                    pbuf[(row * 4 + wn) * 9 + t] = q[t];
            }
        }
    }
    __syncthreads();

    if (tid < 64) {
        int myrow = rowBase + tid;
        if (myrow < NROWS) {
            float m9[9];
#pragma unroll
            for (int t = 0; t < 9; t++)
                m9[t] = pbuf[(tid * 4 + 0) * 9 + t] + pbuf[(tid * 4 + 1) * 9 + t]
                      + pbuf[(tid * 4 + 2) * 9 + t] + pbuf[(tid * 4 + 3) * 9 + t];

            float mat[3][3];
#pragma unroll
            for (int a = 0; a < 3; a++)
#pragma unroll
                for (int b = 0; b < 3; b++)
                    mat[a][b] = m9[a*3 + b] + __ldg(&b2g[a*3 + b]) + (a == b ? 1.0f : 0.0f);

            float rt[3][3];
#pragma unroll
            for (int a = 0; a < 3; a++)
#pragma unroll
                for (int b = 0; b < 3; b++)
                    rt[a][b] = __ldg(&rot[(size_t)myrow * 9 + a*3 + b]);

            float rm[3][3];
#pragma unroll
            for (int a = 0; a < 3; a++)
#pragma unroll
                for (int cc = 0; cc < 3; cc++)
                    rm[a][cc] = mat[a][0]*rt[0][cc] + mat[a][1]*rt[1][cc] + mat[a][2]*rt[2][cc];

            float c0[3], c1[3], c0a[3][3], c1a[3][3];
#pragma unroll
            for (int a = 0; a < 3; a++) {
                c0[a] = rm[a][0];
                c1[a] = rm[a][1];
                c0a[0][a] = -rm[a][1];
                c0a[1][a] = -rm[a][2];
                c0a[2][a] = 0.0f;
                c1a[0][a] = rm[a][0];
                c1a[1][a] = 0.0f;
                c1a[2][a] = -rm[a][2];
            }

            float t0[3], t0a[3][3];
            accp_normalize(c0, c0a, t0, t0a);

            float dot = t0[0]*c1[0] + t0[1]*c1[1] + t0[2]*c1[2];
            float raw1[3], raw1a[3][3];
#pragma unroll
            for (int a = 0; a < 3; a++) raw1[a] = c1[a] - dot * t0[a];
#pragma unroll
            for (int k = 0; k < 3; k++) {
                float dota = 0.0f;
#pragma unroll
                for (int a = 0; a < 3; a++)
                    dota += t0a[k][a]*c1[a] + t0[a]*c1a[k][a];
#pragma unroll
                for (int a = 0; a < 3; a++)
                    raw1a[k][a] = c1a[k][a] - (dota * t0[a] + dot * t0a[k][a]);
            }

            float t1[3], t1a[3][3];
            accp_normalize(raw1, raw1a, t1, t1a);

            const int P1[3] = {1, 2, 0};
            const int P2[3] = {2, 0, 1};
            float t2[3], t2a[3][3];
#pragma unroll
            for (int i = 0; i < 3; i++)
                t2[i] = t0[P1[i]]*t1[P2[i]] - t0[P2[i]]*t1[P1[i]];
#pragma unroll
            for (int k = 0; k < 3; k++)
#pragma unroll
                for (int i = 0; i < 3; i++)
                    t2a[k][i] = t0[P1[i]]*t1a[k][P2[i]] + t0a[k][P1[i]]*t1[P2[i]]
                              - t0[P2[i]]*t1a[k][P1[i]] - t0a[k][P2[i]]*t1[P1[i]];

            float vec[3][3];
#pragma unroll
            for (int k = 0; k < 3; k++) {
                vec[k][0] = t0a[k][0]*t0[1] + t1a[k][0]*t1[1] + t2a[k][0]*t2[1];
                vec[k][1] = t0a[k][0]*t0[2] + t1a[k][0]*t1[2] + t2a[k][0]*t2[2];
                vec[k][2] = t0a[k][1]*t0[2] + t1a[k][1]*t1[2] + t2a[k][1]*t2[2];
            }

            float d00 = vec[1][1]*vec[2][2] - vec[1][2]*vec[2][1];
            float d01 = vec[1][2]*vec[2][0] - vec[1][0]*vec[2][2];
            float d02 = vec[1][0]*vec[2][1] - vec[1][1]*vec[2][0];
            float det = d00*vec[0][0] + d01*vec[0][1] + d02*vec[0][2];
            float logdet = logf(fabsf(det));

            size_t ob = (size_t)myrow * 9;
            out[ob + 0] = t0[0]; out[ob + 1] = t1[0]; out[ob + 2] = t2[0];
            out[ob + 3] = t0[1]; out[ob + 4] = t1[1]; out[ob + 5] = t2[1];
            out[ob + 6] = t0[2]; out[ob + 7] = t1[2]; out[ob + 8] = t2[2];
            out[(size_t)9 * NROWS + myrow] = logdet;
        }
    }
}

extern "C" void kernel_launch(void* const* d_in, const int* in_sizes, int n_in,
                              void* d_out, int out_size) {
    const float* rot  = (const float*)d_in[0];  // rotation [N,3,3]
    const float* feat = (const float*)d_in[1];  // feature  [N,256]
    const float* W1   = (const float*)d_in[2];  // [256,256]
    const float* b1   = (const float*)d_in[3];  // [256]
    const float* W2   = (const float*)d_in[4];  // [256,9]
    const float* b2   = (const float*)d_in[5];  // [9]
    float* out = (float*)d_out;

    cudaFuncSetAttribute(cond9_mma_kernel,
                         cudaFuncAttributeMaxDynamicSharedMemorySize, SMEM_TOTAL);

    prep_bfrag<<<64, 256>>>(W1);
    int blocks = (NROWS + BM - 1) / BM;   // 7813
    cond9_mma_kernel<<<blocks, 256, SMEM_TOTAL>>>(rot, feat, b1, W2, b2, out);
}